// round 2
// baseline (speedup 1.0000x reference)
#include <cuda_runtime.h>
#include <cuda_bf16.h>

// SparseNonzeroAvgPooling:
//   out[r, :] = sum_{m: out_map[m]==r} in_feats[in_map[m], :] / max(count_r, 1)
// C = 32 floats per row (128 B).
//
// Strategy: atomic scatter with red.global.add.v4.f32 (4x fewer atomic ops
// than scalar), 8 threads per kernel-map pair (one float4 each -> coalesced
// 128B row gather), counts in a __device__ global, vectorized divide pass.

#define C_CH 32
#define MAX_NOUT 262144  // >= 250,000, static scratch for counts

__device__ float g_counts[MAX_NOUT];

// ---------------------------------------------------------------------------
// Kernel 1: zero the output buffer (poisoned by harness) and the counts.
// ---------------------------------------------------------------------------
__global__ void zero_kernel(float4* __restrict__ out4, int n_out4, int n_out)
{
    int i = blockIdx.x * blockDim.x + threadIdx.x;
    int stride = gridDim.x * blockDim.x;
    const float4 z = make_float4(0.f, 0.f, 0.f, 0.f);
    for (int k = i; k < n_out4; k += stride) out4[k] = z;
    for (int k = i; k < n_out; k += stride) g_counts[k] = 0.f;
}

// ---------------------------------------------------------------------------
// Kernel 2: scatter-add. 8 threads per pair m; sub-thread s handles float4 #s.
// Grid-stride over pairs so the grid size stays modest.
// ---------------------------------------------------------------------------
__global__ void scatter_kernel(const float4* __restrict__ in_feats4,
                               const int*    __restrict__ in_map,
                               const int*    __restrict__ out_map,
                               float*        __restrict__ out,
                               unsigned int M)
{
    unsigned int t0     = blockIdx.x * blockDim.x + threadIdx.x;
    unsigned int stride = gridDim.x * blockDim.x;
    unsigned int total  = M * 8u;

    for (unsigned int t = t0; t < total; t += stride) {
        unsigned int pair = t >> 3;
        unsigned int sub  = t & 7u;

        int irow = __ldg(in_map  + pair);
        int orow = __ldg(out_map + pair);

        // Coalesced 128B row gather: 8 lanes x 16B contiguous.
        float4 v = __ldg(in_feats4 + (size_t)irow * 8 + sub);

        float* dst = out + (size_t)orow * C_CH + sub * 4;
        asm volatile("red.global.add.v4.f32 [%0], {%1, %2, %3, %4};"
                     :: "l"(dst), "f"(v.x), "f"(v.y), "f"(v.z), "f"(v.w)
                     : "memory");

        if (sub == 0) {
            asm volatile("red.global.add.f32 [%0], %1;"
                         :: "l"(&g_counts[orow]), "f"(1.0f)
                         : "memory");
        }
    }
}

// ---------------------------------------------------------------------------
// Kernel 3: divide each row by max(count, 1). One float4 per thread.
// ---------------------------------------------------------------------------
__global__ void finalize_kernel(float4* __restrict__ out4, int n4)
{
    int i = blockIdx.x * blockDim.x + threadIdx.x;
    if (i >= n4) return;
    int row = i >> 3;                        // 8 float4 per row
    float c = __ldg(&g_counts[row]);
    float inv = 1.0f / fmaxf(c, 1.0f);
    float4 v = out4[i];
    v.x *= inv; v.y *= inv; v.z *= inv; v.w *= inv;
    out4[i] = v;
}

// ---------------------------------------------------------------------------
extern "C" void kernel_launch(void* const* d_in, const int* in_sizes, int n_in,
                              void* d_out, int out_size)
{
    const float4* in_feats4 = (const float4*)d_in[0];
    const int*    in_map    = (const int*)d_in[1];
    const int*    out_map   = (const int*)d_in[2];
    // d_in[3] is n_out (scalar on device); derive on host instead:
    int n_out = out_size / C_CH;
    unsigned int M = (unsigned int)in_sizes[1];

    float*  out  = (float*)d_out;
    float4* out4 = (float4*)d_out;
    int n_out4 = out_size / 4;   // number of float4 elements in output

    // 1. Zero output + counts
    zero_kernel<<<1184, 256>>>(out4, n_out4, n_out);

    // 2. Scatter-add (grid-stride; ~2 iterations per thread at these sizes)
    scatter_kernel<<<65536, 256>>>(in_feats4, in_map, out_map, out, M);

    // 3. Finalize (divide by counts)
    finalize_kernel<<<(n_out4 + 255) / 256, 256>>>(out4, n_out4);
}